// round 2
// baseline (speedup 1.0000x reference)
#include <cuda_runtime.h>

#define GS 7
#define NB 2
#define NC 20
#define CCH 30   // 5*NB + NC

// Zero-initialized at module load; finalize path resets them via atomicExch
// so every graph replay starts clean. No init kernel needed.
__device__ float g_acc[3];
__device__ unsigned int g_count;

__global__ __launch_bounds__(256) void yolo_loss_kernel(
    const float* __restrict__ in_, const float* __restrict__ tg_,
    float* __restrict__ out, int ncells, float inv_bs)
{
    int cell = blockIdx.x * blockDim.x + threadIdx.x;

    float s_box = 0.f, s_conf = 0.f, s_cls = 0.f;

    if (cell < ncells) {
        // 30 floats per cell = 15 float2, always 8B-aligned (120B stride)
        const float2* ip = reinterpret_cast<const float2*>(in_) + (long long)cell * 15;
        const float2* tp = reinterpret_cast<const float2*>(tg_) + (long long)cell * 15;

        float a[10];   // input channels 0..9 (two boxes)
        float t[10];   // target channels 0..9
        #pragma unroll
        for (int i = 0; i < 5; i++) { float2 v = ip[i]; a[2*i] = v.x; a[2*i+1] = v.y; }
        #pragma unroll
        for (int i = 0; i < 5; i++) { float2 v = tp[i]; t[2*i] = v.x; t[2*i+1] = v.y; }

        // Class loss over channels 10..29, accumulated on the fly
        float cls = 0.f;
        #pragma unroll
        for (int i = 5; i < 15; i++) {
            float2 va = ip[i], vt = tp[i];
            float dx = va.x - vt.x, dy = va.y - vt.y;
            cls += dx*dx + dy*dy;
        }

        float conf_t = t[4];
        float coord  = (conf_t > 0.f)  ? 1.f : 0.f;
        float noobj  = (conf_t == 0.f) ? 1.f : 0.f;

        // no-object confidence loss (channels 4 and 9)
        float d0 = a[4] - t[4];
        float d1 = a[9] - t[9];
        float l_noobj = noobj * (d0*d0 + d1*d1);

        // target box -> corners (xy scaled by 1/GS, wh raw)
        float txc = t[0] / 7.f, tyc = t[1] / 7.f, tw = t[2], th = t[3];
        float tx0 = txc - 0.5f*tw, ty0 = tyc - 0.5f*th;
        float tx1 = txc + 0.5f*tw, ty1 = tyc + 0.5f*th;
        float t_area = (tx1 - tx0) * (ty1 - ty0);

        float iou[2];
        #pragma unroll
        for (int b = 0; b < 2; b++) {
            int o = b * 5;
            float px = a[o+0] / 7.f, py = a[o+1] / 7.f, pw = a[o+2], ph = a[o+3];
            float x0 = px - 0.5f*pw, y0 = py - 0.5f*ph;
            float x1 = px + 0.5f*pw, y1 = py + 0.5f*ph;
            float lx = fmaxf(x0, tx0), ly = fmaxf(y0, ty0);
            float rx = fminf(x1, tx1), ry = fminf(y1, ty1);
            float wi = fmaxf(rx - lx, 0.f), hi = fmaxf(ry - ly, 0.f);
            float inter = wi * hi;
            float parea = (x1 - x0) * (y1 - y0);
            iou[b] = inter / (parea + t_area - inter);
        }

        // argmax with first-on-tie semantics (jnp.argmax)
        bool sel1 = iou[1] > iou[0];
        float max_iou = fmaxf(iou[0], iou[1]);
        float r0 = sel1 ? a[5] : a[0];
        float r1 = sel1 ? a[6] : a[1];
        float r2 = sel1 ? a[7] : a[2];
        float r3 = sel1 ? a[8] : a[3];
        float r4 = sel1 ? a[9] : a[4];

        float dx = r0 - t[0], dy = r1 - t[1];
        float sw = sqrtf(r2) - sqrtf(t[2]);
        float sh = sqrtf(r3) - sqrtf(t[3]);
        float dobj = r4 - max_iou;

        s_box  = coord * (dx*dx + dy*dy + sw*sw + sh*sh);   // loss_xy + loss_wh
        s_conf = coord * dobj*dobj + 0.5f * l_noobj;        // loss_obj + 0.5*noobj
        s_cls  = coord * cls;
    }

    // warp reduction
    #pragma unroll
    for (int off = 16; off > 0; off >>= 1) {
        s_box  += __shfl_xor_sync(0xFFFFFFFFu, s_box,  off);
        s_conf += __shfl_xor_sync(0xFFFFFFFFu, s_conf, off);
        s_cls  += __shfl_xor_sync(0xFFFFFFFFu, s_cls,  off);
    }

    __shared__ float sb[3][8];
    int wid = threadIdx.x >> 5, lid = threadIdx.x & 31;
    if (lid == 0) { sb[0][wid] = s_box; sb[1][wid] = s_conf; sb[2][wid] = s_cls; }
    __syncthreads();

    if (threadIdx.x < 3) {
        float s = 0.f;
        #pragma unroll 8
        for (int w = 0; w < 8; w++) s += sb[threadIdx.x][w];
        atomicAdd(&g_acc[threadIdx.x], s);
    }
    __syncthreads();

    // Last-block finalize: read-and-reset accumulators, write outputs.
    if (threadIdx.x == 0) {
        __threadfence();
        unsigned int ticket = atomicAdd(&g_count, 1u);
        if (ticket == gridDim.x - 1) {
            // All other blocks' g_acc adds are fenced-before their counter adds,
            // which happened-before this read. atomicExch reads L2-coherently
            // and resets for the next graph replay.
            float a0 = atomicExch(&g_acc[0], 0.f);
            float a1 = atomicExch(&g_acc[1], 0.f);
            float a2 = atomicExch(&g_acc[2], 0.f);
            out[0] = 0.5f * a0 * inv_bs;   // LAMBDA_COORD * (xy+wh) / bs
            out[1] = a1 * inv_bs;          // (obj + LAMBDA_NOOBJ*noobj) / bs
            out[2] = a2 * inv_bs;          // class / bs
            g_count = 0u;                  // reset for next replay
        }
    }
}

extern "C" void kernel_launch(void* const* d_in, const int* in_sizes, int n_in,
                              void* d_out, int out_size) {
    const float* in_ = (const float*)d_in[0];
    const float* tg_ = (const float*)d_in[1];
    float* out = (float*)d_out;

    int ncells = in_sizes[0] / CCH;               // B * GS * GS
    int bs = ncells / (GS * GS);                  // batch size
    float inv_bs = 1.0f / (float)bs;

    int threads = 256;
    int blocks = (ncells + threads - 1) / threads;
    yolo_loss_kernel<<<blocks, threads>>>(in_, tg_, out, ncells, inv_bs);
}

// round 3
// speedup vs baseline: 1.3137x; 1.3137x over previous
#include <cuda_runtime.h>

#define GS 7
#define NB 2
#define NC 20
#define CCH 30   // 5*NB + NC

// Zero-initialized at module load; finalize kernel resets via atomicExch
// so every graph replay starts clean.
__device__ float g_acc[3];

__global__ __launch_bounds__(256, 2) void yolo_loss_kernel(
    const float* __restrict__ in_, const float* __restrict__ tg_, int ncells)
{
    int cell = blockIdx.x * blockDim.x + threadIdx.x;

    float s_box = 0.f, s_conf = 0.f, s_cls = 0.f;

    if (cell < ncells) {
        // 30 floats per cell = 15 float2, always 8B-aligned (120B stride)
        const float2* ip = reinterpret_cast<const float2*>(in_) + (long long)cell * 15;
        const float2* tp = reinterpret_cast<const float2*>(tg_) + (long long)cell * 15;

        // ---- Front-batch ALL loads before any arithmetic: 30 independent
        // LDG.64 in flight per thread -> latency fully covered.
        float2 va[15], vt[15];
        #pragma unroll
        for (int i = 0; i < 15; i++) va[i] = ip[i];
        #pragma unroll
        for (int i = 0; i < 15; i++) vt[i] = tp[i];

        float a[10], t[10];
        #pragma unroll
        for (int i = 0; i < 5; i++) { a[2*i] = va[i].x; a[2*i+1] = va[i].y; }
        #pragma unroll
        for (int i = 0; i < 5; i++) { t[2*i] = vt[i].x; t[2*i+1] = vt[i].y; }

        // Class loss over channels 10..29
        float cls = 0.f;
        #pragma unroll
        for (int i = 5; i < 15; i++) {
            float dx = va[i].x - vt[i].x, dy = va[i].y - vt[i].y;
            cls += dx*dx + dy*dy;
        }

        float conf_t = t[4];
        float coord  = (conf_t > 0.f)  ? 1.f : 0.f;
        float noobj  = (conf_t == 0.f) ? 1.f : 0.f;

        // no-object confidence loss (channels 4 and 9)
        float d0 = a[4] - t[4];
        float d1 = a[9] - t[9];
        float l_noobj = noobj * (d0*d0 + d1*d1);

        // target box -> corners (xy scaled by 1/GS, wh raw)
        float txc = t[0] / 7.f, tyc = t[1] / 7.f, tw = t[2], th = t[3];
        float tx0 = txc - 0.5f*tw, ty0 = tyc - 0.5f*th;
        float tx1 = txc + 0.5f*tw, ty1 = tyc + 0.5f*th;
        float t_area = (tx1 - tx0) * (ty1 - ty0);

        float iou[2];
        #pragma unroll
        for (int b = 0; b < 2; b++) {
            int o = b * 5;
            float px = a[o+0] / 7.f, py = a[o+1] / 7.f, pw = a[o+2], ph = a[o+3];
            float x0 = px - 0.5f*pw, y0 = py - 0.5f*ph;
            float x1 = px + 0.5f*pw, y1 = py + 0.5f*ph;
            float lx = fmaxf(x0, tx0), ly = fmaxf(y0, ty0);
            float rx = fminf(x1, tx1), ry = fminf(y1, ty1);
            float wi = fmaxf(rx - lx, 0.f), hi = fmaxf(ry - ly, 0.f);
            float inter = wi * hi;
            float parea = (x1 - x0) * (y1 - y0);
            iou[b] = inter / (parea + t_area - inter);
        }

        // argmax with first-on-tie semantics (jnp.argmax)
        bool sel1 = iou[1] > iou[0];
        float max_iou = fmaxf(iou[0], iou[1]);
        float r0 = sel1 ? a[5] : a[0];
        float r1 = sel1 ? a[6] : a[1];
        float r2 = sel1 ? a[7] : a[2];
        float r3 = sel1 ? a[8] : a[3];
        float r4 = sel1 ? a[9] : a[4];

        float dx = r0 - t[0], dy = r1 - t[1];
        float sw = sqrtf(r2) - sqrtf(t[2]);
        float sh = sqrtf(r3) - sqrtf(t[3]);
        float dobj = r4 - max_iou;

        s_box  = coord * (dx*dx + dy*dy + sw*sw + sh*sh);   // loss_xy + loss_wh
        s_conf = coord * dobj*dobj + 0.5f * l_noobj;        // loss_obj + 0.5*noobj
        s_cls  = coord * cls;
    }

    // warp reduction
    #pragma unroll
    for (int off = 16; off > 0; off >>= 1) {
        s_box  += __shfl_xor_sync(0xFFFFFFFFu, s_box,  off);
        s_conf += __shfl_xor_sync(0xFFFFFFFFu, s_conf, off);
        s_cls  += __shfl_xor_sync(0xFFFFFFFFu, s_cls,  off);
    }

    __shared__ float sb[3][8];
    int wid = threadIdx.x >> 5, lid = threadIdx.x & 31;
    if (lid == 0) { sb[0][wid] = s_box; sb[1][wid] = s_conf; sb[2][wid] = s_cls; }
    __syncthreads();

    if (threadIdx.x < 3) {
        float s = 0.f;
        #pragma unroll 8
        for (int w = 0; w < 8; w++) s += sb[threadIdx.x][w];
        atomicAdd(&g_acc[threadIdx.x], s);
    }
}

__global__ void yolo_final_kernel(float* __restrict__ out, float inv_bs) {
    // Read-and-reset so the next graph replay starts from zero.
    float a0 = atomicExch(&g_acc[0], 0.f);
    float a1 = atomicExch(&g_acc[1], 0.f);
    float a2 = atomicExch(&g_acc[2], 0.f);
    out[0] = 0.5f * a0 * inv_bs;   // LAMBDA_COORD * (xy+wh) / bs
    out[1] = a1 * inv_bs;          // (obj + LAMBDA_NOOBJ*noobj) / bs
    out[2] = a2 * inv_bs;          // class / bs
}

extern "C" void kernel_launch(void* const* d_in, const int* in_sizes, int n_in,
                              void* d_out, int out_size) {
    const float* in_ = (const float*)d_in[0];
    const float* tg_ = (const float*)d_in[1];
    float* out = (float*)d_out;

    int ncells = in_sizes[0] / CCH;               // B * GS * GS
    int bs = ncells / (GS * GS);                  // batch size
    float inv_bs = 1.0f / (float)bs;

    int threads = 256;
    int blocks = (ncells + threads - 1) / threads;
    yolo_loss_kernel<<<blocks, threads>>>(in_, tg_, ncells);
    yolo_final_kernel<<<1, 1>>>(out, inv_bs);
}